// round 4
// baseline (speedup 1.0000x reference)
#include <cuda_runtime.h>
#include <math.h>

#define PP 4
#define FP 128
#define HH 512
#define NCLS 60
#define BB 256
#define TT 256
#define TC 4      // time-chunk size (small: __device__ globals are materialized in the ELF)
#define G3 1536   // 3*H
#define NG 13     // 12 part-gate groups + 1 output-gate group

// ---------------- device scratch (static; ~85 MB total so the binary stays small) ----
__device__ float g_G1[TC * BB * PP * G3];   // x-gates cell1, current chunk [tl][b][p][3H]
__device__ float g_G2[TC * BB * PP * G3];   // cell2
__device__ float g_O1[TC * BB * HH];        // o-preact cell1, current chunk [tl][b][h]
__device__ float g_O2[TC * BB * HH];
__device__ float g_Wp1[HH * NG * HH];       // packed recurrent weights [k][g][h]
__device__ float g_Wp2[HH * NG * HH];
__device__ float g_hA[BB * HH];
__device__ float g_hB[BB * HH];
__device__ float g_c[BB * PP * HH];

__device__ __forceinline__ float sigm(float x) { return 1.0f / (1.0f + expf(-x)); }

// ---------------- zero the recurrent state each call ---------------------------
__global__ void zero_state() {
    int i = blockIdx.x * blockDim.x + threadIdx.x;   // grid covers BB*PP*HH
    if (i < BB * HH) g_hA[i] = 0.0f;
    g_c[i] = 0.0f;
}

// ---------------- pack recurrent weights [k][g][h] -----------------------------
// g = p*3+j (j: 0=i,1=f,2=g gate)  for g<12 ;  g==12 -> Who
__global__ void pack_weights(const float* __restrict__ Wh1, const float* __restrict__ Who1,
                             const float* __restrict__ Wh2, const float* __restrict__ Who2) {
    int i = blockIdx.x * blockDim.x + threadIdx.x;
    const int n = HH * NG * HH;
    if (i >= 2 * n) return;
    int cell = i / n;
    int r = i % n;
    int h = r % HH;
    int g = (r / HH) % NG;
    int k = r / (HH * NG);
    const float* Wh  = cell ? Wh2  : Wh1;
    const float* Who = cell ? Who2 : Who1;
    float v;
    if (g < 12) {
        int p = g / 3, j = g % 3;
        v = Wh[((size_t)(p * HH) + k) * G3 + j * HH + h];
    } else {
        v = Who[(size_t)k * HH + h];
    }
    (cell ? g_Wp2 : g_Wp1)[r] = v;
}

// ---------------- input gate GEMM for one time chunk ---------------------------
// G[tl,b,p,n] = x[p,b,t0+tl,:] @ Wx[p,:,n] + bias[p,n]
// M = TC*BB (row r: tl = r>>8, b = r&255), N = 1536, K = 128. Tile 64x64.
__global__ void input_gates(const float* __restrict__ x, const float* __restrict__ Wx,
                            const float* __restrict__ bias, int cell, int t0) {
    __shared__ __align__(16) float As[16][65];
    __shared__ __align__(16) float Ws[16][64];
    const int p  = blockIdx.z;
    const int n0 = blockIdx.x * 64;
    const int r0 = blockIdx.y * 64;
    const int tid = threadIdx.x;

    const int ar = tid >> 2, akq = tid & 3;           // A load map
    const int r  = r0 + ar;
    const int tt = t0 + (r >> 8), bb = r & 255;
    const float* abase = x + ((size_t)(p * BB + bb) * TT + tt) * FP;

    const int wk = tid >> 4, wn4 = tid & 15;          // W load map
    const float* wbase = Wx + (size_t)p * FP * G3 + n0 + wn4 * 4;

    const int tx = tid & 15, ty = tid >> 4;
    float acc[4][4] = {};

    for (int kc = 0; kc < FP; kc += 16) {
        float4 av = *(const float4*)(abase + kc + akq * 4);
        As[akq * 4 + 0][ar] = av.x;
        As[akq * 4 + 1][ar] = av.y;
        As[akq * 4 + 2][ar] = av.z;
        As[akq * 4 + 3][ar] = av.w;
        float4 wv = *(const float4*)(wbase + (size_t)(kc + wk) * G3);
        *(float4*)&Ws[wk][wn4 * 4] = wv;
        __syncthreads();
#pragma unroll
        for (int k = 0; k < 16; k++) {
            float a[4], w[4];
#pragma unroll
            for (int j = 0; j < 4; j++) { a[j] = As[k][ty * 4 + j]; w[j] = Ws[k][tx * 4 + j]; }
#pragma unroll
            for (int i = 0; i < 4; i++)
#pragma unroll
                for (int j = 0; j < 4; j++) acc[i][j] += a[i] * w[j];
        }
        __syncthreads();
    }

    float* out = cell ? g_G2 : g_G1;
#pragma unroll
    for (int i = 0; i < 4; i++) {
        int rr = r0 + ty * 4 + i;
        float4 o;
        o.x = acc[i][0] + bias[p * G3 + n0 + tx * 4 + 0];
        o.y = acc[i][1] + bias[p * G3 + n0 + tx * 4 + 1];
        o.z = acc[i][2] + bias[p * G3 + n0 + tx * 4 + 2];
        o.w = acc[i][3] + bias[p * G3 + n0 + tx * 4 + 3];
        *(float4*)(out + ((size_t)rr * PP + p) * G3 + n0 + tx * 4) = o;
    }
}

// ---------------- input o-gate GEMM for one time chunk -------------------------
// O[tl,b,h] = xflat[b,t0+tl,:] @ Wxo + bo.  M = TC*BB, N = 512, K = 512.
__global__ void input_o(const float* __restrict__ x, const float* __restrict__ Wxo,
                        const float* __restrict__ bo, int cell, int t0) {
    __shared__ __align__(16) float As[16][65];
    __shared__ __align__(16) float Ws[16][64];
    const int n0 = blockIdx.x * 64;
    const int r0 = blockIdx.y * 64;
    const int tid = threadIdx.x;

    const int ar = tid >> 2, akq = tid & 3;
    const int r  = r0 + ar;
    const int tt = t0 + (r >> 8), bb = r & 255;

    const int wk = tid >> 4, wn4 = tid & 15;
    const int tx = tid & 15, ty = tid >> 4;
    float acc[4][4] = {};

    for (int kc = 0; kc < PP * FP; kc += 16) {
        int k = kc + akq * 4;
        int p = k >> 7, f = k & 127;
        float4 av = *(const float4*)(x + ((size_t)(p * BB + bb) * TT + tt) * FP + f);
        As[akq * 4 + 0][ar] = av.x;
        As[akq * 4 + 1][ar] = av.y;
        As[akq * 4 + 2][ar] = av.z;
        As[akq * 4 + 3][ar] = av.w;
        float4 wv = *(const float4*)(Wxo + (size_t)(kc + wk) * HH + n0 + wn4 * 4);
        *(float4*)&Ws[wk][wn4 * 4] = wv;
        __syncthreads();
#pragma unroll
        for (int k2 = 0; k2 < 16; k2++) {
            float a[4], w[4];
#pragma unroll
            for (int j = 0; j < 4; j++) { a[j] = As[k2][ty * 4 + j]; w[j] = Ws[k2][tx * 4 + j]; }
#pragma unroll
            for (int i = 0; i < 4; i++)
#pragma unroll
                for (int j = 0; j < 4; j++) acc[i][j] += a[i] * w[j];
        }
        __syncthreads();
    }

    float* out = cell ? g_O2 : g_O1;
#pragma unroll
    for (int i = 0; i < 4; i++) {
        int rr = r0 + ty * 4 + i;
        float4 o;
        o.x = acc[i][0] + bo[n0 + tx * 4 + 0];
        o.y = acc[i][1] + bo[n0 + tx * 4 + 1];
        o.z = acc[i][2] + bo[n0 + tx * 4 + 2];
        o.w = acc[i][3] + bo[n0 + tx * 4 + 3];
        *(float4*)(out + (size_t)rr * HH + n0 + tx * 4) = o;
    }
}

// ---------------- one LSTM cell step: fused GEMM (13 groups) + pointwise -------
// tl = chunk-local time. grid (H/32, B/32), block 256.
__global__ void lstm_step(int tl, int cell, int hsel) {
    __shared__ __align__(16) float As[16][33];
    __shared__ __align__(16) float Ws[16][NG * 32];

    const float* hin  = hsel ? g_hB : g_hA;
    float*       hout = hsel ? g_hA : g_hB;
    const float* Wp = cell ? g_Wp2 : g_Wp1;
    const float* G  = (cell ? g_G2 : g_G1) + (size_t)tl * BB * PP * G3;
    const float* O  = (cell ? g_O2 : g_O1) + (size_t)tl * BB * HH;

    const int h0 = blockIdx.x * 32;
    const int b0 = blockIdx.y * 32;
    const int tid = threadIdx.x;
    const int hl = tid & 31, bq = tid >> 5;

    float acc[NG][4] = {};

    for (int kc = 0; kc < HH; kc += 16) {
        {   // load A tile (transposed): 32 b x 16 k
            int i = tid;
            int b = i >> 4, k = i & 15;
            As[k][b] = hin[(size_t)(b0 + b) * HH + kc + k];
            i += 256; b = i >> 4; k = i & 15;
            As[k][b] = hin[(size_t)(b0 + b) * HH + kc + k];
        }
        for (int i = tid; i < 16 * NG * 32; i += 256) {   // load W tile: 16k x 13g x 32h
            int hh = i & 31;
            int gk = i >> 5;
            int g = gk % NG, k = gk / NG;
            Ws[k][g * 32 + hh] = Wp[((size_t)(kc + k) * NG + g) * HH + h0 + hh];
        }
        __syncthreads();
#pragma unroll
        for (int k = 0; k < 16; k++) {
            float a[4];
#pragma unroll
            for (int i = 0; i < 4; i++) a[i] = As[k][bq * 4 + i];
#pragma unroll
            for (int g = 0; g < NG; g++) {
                float w = Ws[k][g * 32 + hl];
#pragma unroll
                for (int i = 0; i < 4; i++) acc[g][i] += a[i] * w;
            }
        }
        __syncthreads();
    }

    const int h = h0 + hl;
#pragma unroll
    for (int i = 0; i < 4; i++) {
        const int b = b0 + bq * 4 + i;
        float osum = acc[12][i] + O[(size_t)b * HH + h];
        float csum = 0.0f;
#pragma unroll
        for (int p = 0; p < PP; p++) {
            const float* Gb = G + ((size_t)b * PP + p) * G3 + h;
            float gi = acc[p * 3 + 0][i] + Gb[0];
            float gf = acc[p * 3 + 1][i] + Gb[HH];
            float gg = acc[p * 3 + 2][i] + Gb[2 * HH];
            float* cp = g_c + ((size_t)b * PP + p) * HH + h;
            float cn = sigm(gf) * (*cp) + sigm(gi) * tanhf(gg);
            *cp = cn;
            csum += cn;
        }
        hout[(size_t)b * HH + h] = sigm(osum) * tanhf(csum);
    }
}

// ---------------- classifier + log_softmax ------------------------------------
__global__ void classifier(const float* __restrict__ Wfc, const float* __restrict__ bfc,
                           float* __restrict__ out) {
    __shared__ float hrow[HH];
    __shared__ float lg[NCLS];
    __shared__ float red[2];
    const int b = blockIdx.x;
    const int tid = threadIdx.x;   // 64 threads
    for (int i = tid; i < HH; i += 64) hrow[i] = g_hA[(size_t)b * HH + i];
    __syncthreads();
    if (tid < NCLS) {
        float s = bfc[tid];
        for (int h = 0; h < HH; h++) s += hrow[h] * Wfc[(size_t)h * NCLS + tid];
        lg[tid] = s;
    }
    __syncthreads();
    if (tid == 0) {
        float m = lg[0];
        for (int c = 1; c < NCLS; c++) m = fmaxf(m, lg[c]);
        float s = 0.0f;
        for (int c = 0; c < NCLS; c++) s += expf(lg[c] - m);
        red[0] = m;
        red[1] = logf(s);
    }
    __syncthreads();
    if (tid < NCLS) out[(size_t)b * NCLS + tid] = lg[tid] - red[0] - red[1];
}

// ---------------- launch -------------------------------------------------------
extern "C" void kernel_launch(void* const* d_in, const int* in_sizes, int n_in,
                              void* d_out, int out_size) {
    const float* inputs = (const float*)d_in[0];
    const float* Wx1  = (const float*)d_in[1];
    const float* Wh1  = (const float*)d_in[2];
    const float* b1   = (const float*)d_in[3];
    const float* Wxo1 = (const float*)d_in[4];
    const float* Who1 = (const float*)d_in[5];
    const float* bo1  = (const float*)d_in[6];
    const float* Wx2  = (const float*)d_in[7];
    const float* Wh2  = (const float*)d_in[8];
    const float* b2   = (const float*)d_in[9];
    const float* Wxo2 = (const float*)d_in[10];
    const float* Who2 = (const float*)d_in[11];
    const float* bo2  = (const float*)d_in[12];
    const float* Wfc  = (const float*)d_in[13];
    const float* bfc  = (const float*)d_in[14];
    float* out = (float*)d_out;

    zero_state<<<(BB * PP * HH) / 512, 512>>>();
    pack_weights<<<(2 * HH * NG * HH) / 256, 256>>>(Wh1, Who1, Wh2, Who2);

    dim3 gg(G3 / 64, (TC * BB) / 64, PP);
    dim3 go(HH / 64, (TC * BB) / 64);
    dim3 gs(HH / 32, BB / 32);

    for (int t0 = 0; t0 < TT; t0 += TC) {
        input_gates<<<gg, 256>>>(inputs, Wx1, b1, 0, t0);
        input_gates<<<gg, 256>>>(inputs, Wx2, b2, 1, t0);
        input_o<<<go, 256>>>(inputs, Wxo1, bo1, 0, t0);
        input_o<<<go, 256>>>(inputs, Wxo2, bo2, 1, t0);
        for (int tl = 0; tl < TC; tl++) {
            lstm_step<<<gs, 256>>>(tl, 0, 0);   // cell1: reads hA, writes hB
            lstm_step<<<gs, 256>>>(tl, 1, 1);   // cell2: reads hB, writes hA
        }
    }

    classifier<<<BB, 64>>>(Wfc, bfc, out);
}

// round 11
// speedup vs baseline: 3.5689x; 3.5689x over previous
#include <cuda_runtime.h>
#include <cuda_bf16.h>
#include <cstdint>
#include <math.h>

#define PP 4
#define FP 128
#define HH 512
#define NCLS 60
#define BB 256
#define TT 256
#define TC 4      // time-chunk size for input precompute scratch
#define G3 1536   // 3*H
#define NG 13     // 12 part-gate groups + 1 output-gate group
#define NROWS 104 // NG*8 weight rows per h-tile

// smem stage (KC=32, 64-byte rows): Ahi 4096 | Alo 4096 | Bhi 6656 | Blo 6656
#define OFF_ALO 4096
#define OFF_BHI 8192
#define OFF_BLO 14848
#define STAGE_BYTES 21504
// 2 stages = 43008 bytes -> fits STATIC shared (<48KB): no SetAttribute needed.

// ---------------- device scratch (~77 MB total) --------------------------------
__device__ float g_G1[TC * BB * PP * G3];   // x-gate preacts cell1 [tl][b][p][3H]
__device__ float g_G2[TC * BB * PP * G3];
__device__ float g_O1[TC * BB * HH];        // o-gate x-preacts [tl][b][h]
__device__ float g_O2[TC * BB * HH];
// packed recurrent weights bf16 hi/lo: [nglobal][k], nglobal = ht*104 + g*8 + hl
__device__ __nv_bfloat16 g_W1hi[64 * NROWS * HH];
__device__ __nv_bfloat16 g_W1lo[64 * NROWS * HH];
__device__ __nv_bfloat16 g_W2hi[64 * NROWS * HH];
__device__ __nv_bfloat16 g_W2lo[64 * NROWS * HH];
// hidden state: fp32 (classifier) + bf16 hi/lo ping-pong (GEMM operands)
__device__ float g_h[BB * HH];
__device__ __nv_bfloat16 g_hhiA[BB * HH];
__device__ __nv_bfloat16 g_hloA[BB * HH];
__device__ __nv_bfloat16 g_hhiB[BB * HH];
__device__ __nv_bfloat16 g_hloB[BB * HH];
__device__ float g_c[BB * PP * HH];

__device__ __forceinline__ float sigm(float x) { return 1.0f / (1.0f + __expf(-x)); }

__device__ __forceinline__ uint32_t smem_u32(const void* p) {
    uint32_t a;
    asm("{ .reg .u64 t; cvta.to.shared.u64 t, %1; cvt.u32.u64 %0, t; }" : "=r"(a) : "l"(p));
    return a;
}

// SW64 swizzle for 64-byte rows (8 rows x 64B atom); keeps offset inside its row.
#define SW64(o) ((o) ^ (((o) >> 3) & 0x30))

__device__ __forceinline__ void cp16(uint32_t saddr, const void* g) {
    asm volatile("cp.async.cg.shared.global [%0], [%1], 16;" :: "r"(saddr), "l"(g));
}
__device__ __forceinline__ void ldmx4(uint32_t* r, uint32_t addr) {
    asm volatile("ldmatrix.sync.aligned.m8n8.x4.shared.b16 {%0,%1,%2,%3}, [%4];"
        : "=r"(r[0]), "=r"(r[1]), "=r"(r[2]), "=r"(r[3]) : "r"(addr));
}
__device__ __forceinline__ void mma16816(float* c, const uint32_t* a, uint32_t b0, uint32_t b1) {
    asm volatile("mma.sync.aligned.m16n8k16.row.col.f32.bf16.bf16.f32 "
        "{%0,%1,%2,%3}, {%4,%5,%6,%7}, {%8,%9}, {%0,%1,%2,%3};"
        : "+f"(c[0]), "+f"(c[1]), "+f"(c[2]), "+f"(c[3])
        : "r"(a[0]), "r"(a[1]), "r"(a[2]), "r"(a[3]), "r"(b0), "r"(b1));
}

// ---------------- zero recurrent state -----------------------------------------
__global__ void zero_state() {
    int i = blockIdx.x * blockDim.x + threadIdx.x;   // grid covers BB*PP*HH
    g_c[i] = 0.0f;
    if (i < BB * HH) {
        g_h[i] = 0.0f;
        __nv_bfloat16 z = __float2bfloat16(0.0f);
        g_hhiA[i] = z; g_hloA[i] = z; g_hhiB[i] = z; g_hloB[i] = z;
    }
}

// ---------------- pack + split recurrent weights -------------------------------
// nglobal = ht*104 + g*8 + hl ; h = ht*8 + hl ; g = 3p+j (j in {i,f,g}), 12 -> Who
__global__ void pack_weights(const float* __restrict__ Wh1, const float* __restrict__ Who1,
                             const float* __restrict__ Wh2, const float* __restrict__ Who2) {
    int i = blockIdx.x * blockDim.x + threadIdx.x;
    const int n = 64 * NROWS * HH;
    if (i >= 2 * n) return;
    int cell = i / n;
    int r = i % n;
    int k  = r & (HH - 1);
    int ng = r >> 9;
    int ht = ng / NROWS;
    int nl = ng % NROWS;
    int g  = nl >> 3, hl = nl & 7;
    int h  = ht * 8 + hl;
    const float* Wh  = cell ? Wh2  : Wh1;
    const float* Who = cell ? Who2 : Who1;
    float v;
    if (g < 12) {
        int p = g / 3, j = g % 3;
        v = Wh[((size_t)(p * HH) + k) * G3 + j * HH + h];
    } else {
        v = Who[(size_t)k * HH + h];
    }
    __nv_bfloat16 hi = __float2bfloat16(v);
    __nv_bfloat16 lo = __float2bfloat16(v - __bfloat162float(hi));
    (cell ? g_W2hi : g_W1hi)[r] = hi;
    (cell ? g_W2lo : g_W1lo)[r] = lo;
}

// ---------------- input gate GEMM, both cells (z = p + 4*cell) -----------------
__global__ void input_gates(const float* __restrict__ x,
                            const float* __restrict__ Wx1c, const float* __restrict__ Wx2c,
                            const float* __restrict__ b1c, const float* __restrict__ b2c,
                            int t0) {
    __shared__ __align__(16) float As[16][65];
    __shared__ __align__(16) float Ws[16][64];
    const int cell = blockIdx.z >> 2;
    const int p  = blockIdx.z & 3;
    const float* Wx  = cell ? Wx2c : Wx1c;
    const float* bias = cell ? b2c : b1c;
    const int n0 = blockIdx.x * 64;
    const int r0 = blockIdx.y * 64;
    const int tid = threadIdx.x;

    const int ar = tid >> 2, akq = tid & 3;
    const int r  = r0 + ar;
    const int tt = t0 + (r >> 8), bb = r & 255;
    const float* abase = x + ((size_t)(p * BB + bb) * TT + tt) * FP;

    const int wk = tid >> 4, wn4 = tid & 15;
    const float* wbase = Wx + (size_t)p * FP * G3 + n0 + wn4 * 4;

    const int tx = tid & 15, ty = tid >> 4;
    float acc[4][4] = {};

    for (int kc = 0; kc < FP; kc += 16) {
        float4 av = *(const float4*)(abase + kc + akq * 4);
        As[akq * 4 + 0][ar] = av.x;
        As[akq * 4 + 1][ar] = av.y;
        As[akq * 4 + 2][ar] = av.z;
        As[akq * 4 + 3][ar] = av.w;
        float4 wv = *(const float4*)(wbase + (size_t)(kc + wk) * G3);
        *(float4*)&Ws[wk][wn4 * 4] = wv;
        __syncthreads();
#pragma unroll
        for (int k = 0; k < 16; k++) {
            float a[4], w[4];
#pragma unroll
            for (int j = 0; j < 4; j++) { a[j] = As[k][ty * 4 + j]; w[j] = Ws[k][tx * 4 + j]; }
#pragma unroll
            for (int i = 0; i < 4; i++)
#pragma unroll
                for (int j = 0; j < 4; j++) acc[i][j] += a[i] * w[j];
        }
        __syncthreads();
    }

    float* out = cell ? g_G2 : g_G1;
#pragma unroll
    for (int i = 0; i < 4; i++) {
        int rr = r0 + ty * 4 + i;
        float4 o;
        o.x = acc[i][0] + bias[p * G3 + n0 + tx * 4 + 0];
        o.y = acc[i][1] + bias[p * G3 + n0 + tx * 4 + 1];
        o.z = acc[i][2] + bias[p * G3 + n0 + tx * 4 + 2];
        o.w = acc[i][3] + bias[p * G3 + n0 + tx * 4 + 3];
        *(float4*)(out + ((size_t)rr * PP + p) * G3 + n0 + tx * 4) = o;
    }
}

// ---------------- input o-gate GEMM, both cells (z = cell) ---------------------
__global__ void input_o(const float* __restrict__ x,
                        const float* __restrict__ Wxo1c, const float* __restrict__ Wxo2c,
                        const float* __restrict__ bo1c, const float* __restrict__ bo2c,
                        int t0) {
    __shared__ __align__(16) float As[16][65];
    __shared__ __align__(16) float Ws[16][64];
    const int cell = blockIdx.z;
    const float* Wxo = cell ? Wxo2c : Wxo1c;
    const float* bo  = cell ? bo2c : bo1c;
    const int n0 = blockIdx.x * 64;
    const int r0 = blockIdx.y * 64;
    const int tid = threadIdx.x;

    const int ar = tid >> 2, akq = tid & 3;
    const int r  = r0 + ar;
    const int tt = t0 + (r >> 8), bb = r & 255;

    const int wk = tid >> 4, wn4 = tid & 15;
    const int tx = tid & 15, ty = tid >> 4;
    float acc[4][4] = {};

    for (int kc = 0; kc < PP * FP; kc += 16) {
        int k = kc + akq * 4;
        int p = k >> 7, f = k & 127;
        float4 av = *(const float4*)(x + ((size_t)(p * BB + bb) * TT + tt) * FP + f);
        As[akq * 4 + 0][ar] = av.x;
        As[akq * 4 + 1][ar] = av.y;
        As[akq * 4 + 2][ar] = av.z;
        As[akq * 4 + 3][ar] = av.w;
        float4 wv = *(const float4*)(Wxo + (size_t)(kc + wk) * HH + n0 + wn4 * 4);
        *(float4*)&Ws[wk][wn4 * 4] = wv;
        __syncthreads();
#pragma unroll
        for (int k2 = 0; k2 < 16; k2++) {
            float a[4], w[4];
#pragma unroll
            for (int j = 0; j < 4; j++) { a[j] = As[k2][ty * 4 + j]; w[j] = Ws[k2][tx * 4 + j]; }
#pragma unroll
            for (int i = 0; i < 4; i++)
#pragma unroll
                for (int j = 0; j < 4; j++) acc[i][j] += a[i] * w[j];
        }
        __syncthreads();
    }

    float* out = cell ? g_O2 : g_O1;
#pragma unroll
    for (int i = 0; i < 4; i++) {
        int rr = r0 + ty * 4 + i;
        float4 o;
        o.x = acc[i][0] + bo[n0 + tx * 4 + 0];
        o.y = acc[i][1] + bo[n0 + tx * 4 + 1];
        o.z = acc[i][2] + bo[n0 + tx * 4 + 2];
        o.w = acc[i][3] + bo[n0 + tx * 4 + 3];
        *(float4*)(out + (size_t)rr * HH + n0 + tx * 4) = o;
    }
}

// ---------------- stage loader for lstm_step_mma -------------------------------
__device__ __forceinline__ void load_stage(
    uint32_t sbase, int c, int tid,
    const __nv_bfloat16* hhi, const __nv_bfloat16* hlo,
    const __nv_bfloat16* Whi, const __nv_bfloat16* Wlo,
    size_t brow0, size_t wb) {
    const int kc = c * 32;
    const uint32_t sp = sbase + (uint32_t)(c & 1) * STAGE_BYTES;
    // A hi/lo: 64 rows x 4 x 16B
    for (int i = tid; i < 256; i += 128) {
        int row = i >> 2, q = i & 3;
        size_t go = (brow0 + (size_t)row) * HH + kc + q * 8;
        uint32_t so = SW64((uint32_t)(row * 64 + q * 16));
        cp16(sp + so, hhi + go);
        cp16(sp + OFF_ALO + so, hlo + go);
    }
    // B hi/lo: 104 rows x 4 x 16B
    for (int i = tid; i < 416; i += 128) {
        int row = i >> 2, q = i & 3;
        size_t go = (wb + (size_t)row) * HH + kc + q * 8;
        uint32_t so = SW64((uint32_t)(row * 64 + q * 16));
        cp16(sp + OFF_BHI + so, Whi + go);
        cp16(sp + OFF_BLO + so, Wlo + go);
    }
    asm volatile("cp.async.commit_group;" ::: "memory");
}

// ---------------- mma.sync LSTM step ------------------------------------------
// grid (64 h-tiles, 4 b-tiles), 128 threads (4 warps x 16-row M tiles).
// Per CTA: D[64b, 104n] = h[64,512] @ Wp^T via bf16 m16n8k16, 3-term split.
// Static 43KB shared, double-buffered cp.async, KC=32, SW64.
__global__ void __launch_bounds__(128, 1) lstm_step_mma(int tl, int cell, int hsel) {
    __shared__ __align__(128) char smem[2 * STAGE_BYTES];
    const int tid = threadIdx.x;
    const int wid = tid >> 5;
    const int lane = tid & 31;
    const int bx = blockIdx.x;                  // h-tile index (8 h per tile)
    const size_t brow0 = (size_t)blockIdx.y * 64;

    const __nv_bfloat16* hhi = hsel ? g_hhiB : g_hhiA;
    const __nv_bfloat16* hlo = hsel ? g_hloB : g_hloA;
    __nv_bfloat16* ohhi = hsel ? g_hhiA : g_hhiB;
    __nv_bfloat16* ohlo = hsel ? g_hloA : g_hloB;
    const __nv_bfloat16* Whi = cell ? g_W2hi : g_W1hi;
    const __nv_bfloat16* Wlo = cell ? g_W2lo : g_W1lo;
    const float* G = (cell ? g_G2 : g_G1) + (size_t)tl * BB * PP * G3;
    const float* O = (cell ? g_O2 : g_O1) + (size_t)tl * BB * HH;

    const uint32_t sbase = smem_u32(smem);
    const size_t wb = (size_t)bx * NROWS;

    float acc[NG][4] = {};

    load_stage(sbase, 0, tid, hhi, hlo, Whi, Wlo, brow0, wb);
    for (int c = 0; c < 16; c++) {
        if (c < 15) {
            load_stage(sbase, c + 1, tid, hhi, hlo, Whi, Wlo, brow0, wb);
            asm volatile("cp.async.wait_group 1;" ::: "memory");
        } else {
            asm volatile("cp.async.wait_group 0;" ::: "memory");
        }
        __syncthreads();

        const uint32_t sp = sbase + (uint32_t)(c & 1) * STAGE_BYTES;
        const uint32_t arow = (uint32_t)(wid * 16 + (lane & 15));
        uint32_t ahi[2][4], alo[2][4];
#pragma unroll
        for (int ks = 0; ks < 2; ks++) {
            uint32_t ab = SW64(arow * 64 + (uint32_t)(ks * 32) + ((uint32_t)(lane >> 4) << 4));
            ldmx4(ahi[ks], sp + ab);
            ldmx4(alo[ks], sp + OFF_ALO + ab);
        }
#pragma unroll
        for (int g = 0; g < NG; g++) {
            uint32_t bb = SW64((uint32_t)(g * 8 + (lane & 7)) * 64 + ((uint32_t)(lane >> 3) << 4));
            uint32_t bhi[4], blo[4];
            ldmx4(bhi, sp + OFF_BHI + bb);
            ldmx4(blo, sp + OFF_BLO + bb);
            mma16816(acc[g], ahi[0], bhi[0], bhi[1]);
            mma16816(acc[g], ahi[1], bhi[2], bhi[3]);
            mma16816(acc[g], alo[0], bhi[0], bhi[1]);
            mma16816(acc[g], alo[1], bhi[2], bhi[3]);
            mma16816(acc[g], ahi[0], blo[0], blo[1]);
            mma16816(acc[g], ahi[1], blo[2], blo[3]);
        }
        __syncthreads();   // protect buffer before the next-next stage overwrites
    }

    // ---- fused epilogue: fragment (ri,cj) -> (b, h); all 13 groups in regs ----
    const int h0 = bx * 8;
#pragma unroll
    for (int ri = 0; ri < 2; ri++) {
#pragma unroll
        for (int cj = 0; cj < 2; cj++) {
            const int idx = ri * 2 + cj;
            const int b = (int)brow0 + wid * 16 + (lane >> 2) + ri * 8;
            const int h = h0 + (lane & 3) * 2 + cj;
            float osum = acc[12][idx] + O[(size_t)b * HH + h];
            float csum = 0.0f;
#pragma unroll
            for (int p = 0; p < PP; p++) {
                const float* Gp = G + ((size_t)b * PP + p) * G3 + h;
                float gi = acc[p * 3 + 0][idx] + Gp[0 * HH];
                float gf = acc[p * 3 + 1][idx] + Gp[1 * HH];
                float gg = acc[p * 3 + 2][idx] + Gp[2 * HH];
                float* cp = g_c + ((size_t)b * PP + p) * HH + h;
                float cn = sigm(gf) * (*cp) + sigm(gi) * tanhf(gg);
                *cp = cn;
                csum += cn;
            }
            float hv = sigm(osum) * tanhf(csum);
            size_t oidx = (size_t)b * HH + h;
            g_h[oidx] = hv;
            __nv_bfloat16 hi = __float2bfloat16(hv);
            __nv_bfloat16 lo = __float2bfloat16(hv - __bfloat162float(hi));
            ohhi[oidx] = hi;
            ohlo[oidx] = lo;
        }
    }
}

// ---------------- classifier + log_softmax ------------------------------------
__global__ void classifier(const float* __restrict__ Wfc, const float* __restrict__ bfc,
                           float* __restrict__ out) {
    __shared__ float hrow[HH];
    __shared__ float lg[NCLS];
    __shared__ float red[2];
    const int b = blockIdx.x;
    const int tid = threadIdx.x;   // 64 threads
    for (int i = tid; i < HH; i += 64) hrow[i] = g_h[(size_t)b * HH + i];
    __syncthreads();
    if (tid < NCLS) {
        float s = bfc[tid];
        for (int h = 0; h < HH; h++) s += hrow[h] * Wfc[(size_t)h * NCLS + tid];
        lg[tid] = s;
    }
    __syncthreads();
    if (tid == 0) {
        float m = lg[0];
        for (int c = 1; c < NCLS; c++) m = fmaxf(m, lg[c]);
        float s = 0.0f;
        for (int c = 0; c < NCLS; c++) s += expf(lg[c] - m);
        red[0] = m;
        red[1] = logf(s);
    }
    __syncthreads();
    if (tid < NCLS) out[(size_t)b * NCLS + tid] = lg[tid] - red[0] - red[1];
}

// ---------------- launch -------------------------------------------------------
extern "C" void kernel_launch(void* const* d_in, const int* in_sizes, int n_in,
                              void* d_out, int out_size) {
    const float* inputs = (const float*)d_in[0];
    const float* Wx1  = (const float*)d_in[1];
    const float* Wh1  = (const float*)d_in[2];
    const float* b1   = (const float*)d_in[3];
    const float* Wxo1 = (const float*)d_in[4];
    const float* Who1 = (const float*)d_in[5];
    const float* bo1  = (const float*)d_in[6];
    const float* Wx2  = (const float*)d_in[7];
    const float* Wh2  = (const float*)d_in[8];
    const float* b2   = (const float*)d_in[9];
    const float* Wxo2 = (const float*)d_in[10];
    const float* Who2 = (const float*)d_in[11];
    const float* bo2  = (const float*)d_in[12];
    const float* Wfc  = (const float*)d_in[13];
    const float* bfc  = (const float*)d_in[14];
    float* out = (float*)d_out;

    zero_state<<<(BB * PP * HH) / 512, 512>>>();
    pack_weights<<<(2 * 64 * NROWS * HH) / 256, 256>>>(Wh1, Who1, Wh2, Who2);

    dim3 gg(G3 / 64, (TC * BB) / 64, PP * 2);
    dim3 go(HH / 64, (TC * BB) / 64, 2);
    dim3 gs(64, 4);

    for (int t0 = 0; t0 < TT; t0 += TC) {
        input_gates<<<gg, 256>>>(inputs, Wx1, Wx2, b1, b2, t0);
        input_o<<<go, 256>>>(inputs, Wxo1, Wxo2, bo1, bo2, t0);
        for (int tl = 0; tl < TC; tl++) {
            lstm_step_mma<<<gs, 128>>>(tl, 0, 0);   // cell1: reads A, writes B
            lstm_step_mma<<<gs, 128>>>(tl, 1, 1);   // cell2: reads B, writes A
        }
    }

    classifier<<<BB, 64>>>(Wfc, bfc, out);
}